// round 1
// baseline (speedup 1.0000x reference)
#include <cuda_runtime.h>
#include <math.h>

#define BATCH   4
#define CCH     512
#define NSP     4096        // 64*64 spatial
#define NGROUPS 32
#define CPG     16          // channels per group

// -------- scratch (static device globals; allocation-free at runtime) --------
__device__ float g_hn[(size_t)BATCH * CCH * NSP];                 // 32 MB
__device__ float g_q [(size_t)BATCH * CCH * NSP];                 // 32 MB
__device__ float g_k [(size_t)BATCH * CCH * NSP];                 // 32 MB
__device__ float g_v [(size_t)BATCH * CCH * NSP];                 // 32 MB
__device__ float g_o [(size_t)BATCH * CCH * NSP];                 // 32 MB
__device__ float g_attn[(size_t)BATCH * NSP * NSP];               // 256 MB

// ============================ GroupNorm ============================
// One block per (batch, group). Group = 16 channels x 4096 = 65536 floats.
__global__ void __launch_bounds__(256) groupnorm_kernel(
    const float* __restrict__ x,
    const float* __restrict__ gamma,
    const float* __restrict__ beta)
{
    const int b = blockIdx.x >> 5;
    const int g = blockIdx.x & 31;
    const size_t base = ((size_t)b * CCH + (size_t)g * CPG) * NSP;
    const float4* xp = reinterpret_cast<const float4*>(x + base);
    float4*       hp = reinterpret_cast<float4*>(g_hn + base);
    const int nv = CPG * NSP / 4;   // 16384 float4

    float s = 0.f, ss = 0.f;
    for (int i = threadIdx.x; i < nv; i += 256) {
        float4 v = xp[i];
        s  += v.x + v.y + v.z + v.w;
        ss += v.x*v.x + v.y*v.y + v.z*v.z + v.w*v.w;
    }
    __shared__ float rs[256], rq[256];
    rs[threadIdx.x] = s; rq[threadIdx.x] = ss;
    __syncthreads();
    #pragma unroll
    for (int o = 128; o > 0; o >>= 1) {
        if (threadIdx.x < o) {
            rs[threadIdx.x] += rs[threadIdx.x + o];
            rq[threadIdx.x] += rq[threadIdx.x + o];
        }
        __syncthreads();
    }
    const float inv_n = 1.f / (float)(CPG * NSP);
    const float mean = rs[0] * inv_n;
    const float var  = rq[0] * inv_n - mean * mean;
    const float inv  = rsqrtf(var + 1e-6f);

    for (int i = threadIdx.x; i < nv; i += 256) {
        const int c = g * CPG + (i >> 10);   // 1024 float4 per channel
        const float ga = gamma[c] * inv;
        const float be = beta[c] - mean * ga;
        float4 v = xp[i];
        v.x = v.x * ga + be;
        v.y = v.y * ga + be;
        v.z = v.z * ga + be;
        v.w = v.w * ga + be;
        hp[i] = v;
    }
}

// ============================ conv GEMM ============================
// out[b][m][n] = sum_k W[m][k] * X[b][k][n] + bias[m] (+ res[b][m][n])
// M = K = 512, N = 4096. 64x64 tile, K-tile 16, 256 threads, 4x4 per thread.
__global__ void __launch_bounds__(256) conv_gemm(
    const float* __restrict__ W,
    const float* __restrict__ X,
    const float* __restrict__ bias,
    const float* __restrict__ res,
    float* __restrict__ out)
{
    const int b = blockIdx.z;
    X   += (size_t)b * CCH * NSP;
    out += (size_t)b * CCH * NSP;
    if (res) res += (size_t)b * CCH * NSP;

    const int m0 = blockIdx.y * 64, n0 = blockIdx.x * 64;
    __shared__ float Ws[16][68];   // [k][m], padded
    __shared__ float Xs[16][68];   // [k][n], padded

    const int tid = threadIdx.x;
    const int tx = tid & 15, ty = tid >> 4;
    const int wr = tid >> 2, wq = tid & 3;    // W: row within m-tile, k-quad
    const int xk = tid >> 4, xq = tid & 15;   // X: k-row, n-quad

    float acc[4][4] = {};

    for (int k0 = 0; k0 < CCH; k0 += 16) {
        const float4 wv = *reinterpret_cast<const float4*>(W + (size_t)(m0 + wr) * CCH + k0 + wq * 4);
        const float4 xv = *reinterpret_cast<const float4*>(X + (size_t)(k0 + xk) * NSP + n0 + xq * 4);
        __syncthreads();
        Ws[wq*4+0][wr] = wv.x; Ws[wq*4+1][wr] = wv.y;
        Ws[wq*4+2][wr] = wv.z; Ws[wq*4+3][wr] = wv.w;
        *reinterpret_cast<float4*>(&Xs[xk][xq*4]) = xv;
        __syncthreads();
        #pragma unroll
        for (int kk = 0; kk < 16; kk++) {
            const float4 a  = *reinterpret_cast<const float4*>(&Ws[kk][ty*4]);
            const float4 bb = *reinterpret_cast<const float4*>(&Xs[kk][tx*4]);
            const float ar[4] = {a.x, a.y, a.z, a.w};
            const float br[4] = {bb.x, bb.y, bb.z, bb.w};
            #pragma unroll
            for (int i = 0; i < 4; i++)
                #pragma unroll
                for (int j = 0; j < 4; j++)
                    acc[i][j] = fmaf(ar[i], br[j], acc[i][j]);
        }
    }

    #pragma unroll
    for (int i = 0; i < 4; i++) {
        const int row = m0 + ty * 4 + i;
        const float bi = bias[row];
        float* op = out + (size_t)row * NSP + n0 + tx * 4;
        #pragma unroll
        for (int j = 0; j < 4; j++) {
            float v = acc[i][j] + bi;
            if (res) v += res[(size_t)row * NSP + n0 + tx * 4 + j];
            op[j] = v;
        }
    }
}

// ============================ scores GEMM ============================
// S[b][n][m] = scale * sum_c Q[b][c][n] * K[b][c][m]
__global__ void __launch_bounds__(256) scores_gemm()
{
    const int b = blockIdx.z;
    const float* Q  = g_q + (size_t)b * CCH * NSP;
    const float* Kp = g_k + (size_t)b * CCH * NSP;
    float*       S  = g_attn + (size_t)b * NSP * NSP;

    const int n0 = blockIdx.y * 64, m0 = blockIdx.x * 64;
    __shared__ float Qs[16][68];
    __shared__ float Ks[16][68];

    const int tid = threadIdx.x;
    const int tx = tid & 15, ty = tid >> 4;
    const int lk = tid >> 4, lq = tid & 15;

    float acc[4][4] = {};

    for (int k0 = 0; k0 < CCH; k0 += 16) {
        const float4 qv = *reinterpret_cast<const float4*>(Q  + (size_t)(k0 + lk) * NSP + n0 + lq * 4);
        const float4 kv = *reinterpret_cast<const float4*>(Kp + (size_t)(k0 + lk) * NSP + m0 + lq * 4);
        __syncthreads();
        *reinterpret_cast<float4*>(&Qs[lk][lq*4]) = qv;
        *reinterpret_cast<float4*>(&Ks[lk][lq*4]) = kv;
        __syncthreads();
        #pragma unroll
        for (int kk = 0; kk < 16; kk++) {
            const float4 a  = *reinterpret_cast<const float4*>(&Qs[kk][ty*4]);
            const float4 bb = *reinterpret_cast<const float4*>(&Ks[kk][tx*4]);
            const float ar[4] = {a.x, a.y, a.z, a.w};
            const float br[4] = {bb.x, bb.y, bb.z, bb.w};
            #pragma unroll
            for (int i = 0; i < 4; i++)
                #pragma unroll
                for (int j = 0; j < 4; j++)
                    acc[i][j] = fmaf(ar[i], br[j], acc[i][j]);
        }
    }

    const float scale = 0.04419417382415922f;   // 512^-0.5
    #pragma unroll
    for (int i = 0; i < 4; i++) {
        float* sp = S + (size_t)(n0 + ty * 4 + i) * NSP + m0 + tx * 4;
        #pragma unroll
        for (int j = 0; j < 4; j++) sp[j] = acc[i][j] * scale;
    }
}

// ============================ softmax ============================
// One block per (b, n) row of 4096; row lives entirely in registers.
__global__ void __launch_bounds__(256) softmax_kernel()
{
    float* p = g_attn + (size_t)blockIdx.x * NSP;
    const int tid = threadIdx.x;

    float4 v[4];
    float mx = -3.4e38f;
    #pragma unroll
    for (int i = 0; i < 4; i++) {
        v[i] = reinterpret_cast<float4*>(p)[tid + i * 256];
        mx = fmaxf(mx, fmaxf(fmaxf(v[i].x, v[i].y), fmaxf(v[i].z, v[i].w)));
    }

    __shared__ float red[8];
    __shared__ float bval;
    #pragma unroll
    for (int o = 16; o > 0; o >>= 1) mx = fmaxf(mx, __shfl_xor_sync(0xffffffffu, mx, o));
    if ((tid & 31) == 0) red[tid >> 5] = mx;
    __syncthreads();
    if (tid < 8) {
        float m = red[tid];
        #pragma unroll
        for (int o = 4; o > 0; o >>= 1) m = fmaxf(m, __shfl_xor_sync(0xffu, m, o));
        if (tid == 0) bval = m;
    }
    __syncthreads();
    mx = bval;

    float sum = 0.f;
    #pragma unroll
    for (int i = 0; i < 4; i++) {
        v[i].x = expf(v[i].x - mx); v[i].y = expf(v[i].y - mx);
        v[i].z = expf(v[i].z - mx); v[i].w = expf(v[i].w - mx);
        sum += v[i].x + v[i].y + v[i].z + v[i].w;
    }
    #pragma unroll
    for (int o = 16; o > 0; o >>= 1) sum += __shfl_xor_sync(0xffffffffu, sum, o);
    __syncthreads();
    if ((tid & 31) == 0) red[tid >> 5] = sum;
    __syncthreads();
    if (tid < 8) {
        float s2 = red[tid];
        #pragma unroll
        for (int o = 4; o > 0; o >>= 1) s2 += __shfl_xor_sync(0xffu, s2, o);
        if (tid == 0) bval = s2;
    }
    __syncthreads();

    const float r = 1.f / bval;
    #pragma unroll
    for (int i = 0; i < 4; i++) {
        v[i].x *= r; v[i].y *= r; v[i].z *= r; v[i].w *= r;
        reinterpret_cast<float4*>(p)[tid + i * 256] = v[i];
    }
}

// ============================ attn * V GEMM ============================
// O[b][c][n] = sum_m V[b][c][m] * A[b][n][m]   (K = 4096)
__global__ void __launch_bounds__(256) av_gemm()
{
    const int b = blockIdx.z;
    const float* V = g_v + (size_t)b * CCH * NSP;
    const float* A = g_attn + (size_t)b * NSP * NSP;
    float*       O = g_o + (size_t)b * CCH * NSP;

    const int c0 = blockIdx.y * 64, n0 = blockIdx.x * 64;
    __shared__ float Vs[16][68];   // [m][c]
    __shared__ float As[16][68];   // [m][n]

    const int tid = threadIdx.x;
    const int tx = tid & 15, ty = tid >> 4;
    const int r = tid >> 2, q = tid & 3;

    float acc[4][4] = {};

    for (int k0 = 0; k0 < NSP; k0 += 16) {
        const float4 vv = *reinterpret_cast<const float4*>(V + (size_t)(c0 + r) * NSP + k0 + q * 4);
        const float4 av = *reinterpret_cast<const float4*>(A + (size_t)(n0 + r) * NSP + k0 + q * 4);
        __syncthreads();
        Vs[q*4+0][r] = vv.x; Vs[q*4+1][r] = vv.y;
        Vs[q*4+2][r] = vv.z; Vs[q*4+3][r] = vv.w;
        As[q*4+0][r] = av.x; As[q*4+1][r] = av.y;
        As[q*4+2][r] = av.z; As[q*4+3][r] = av.w;
        __syncthreads();
        #pragma unroll
        for (int kk = 0; kk < 16; kk++) {
            const float4 a  = *reinterpret_cast<const float4*>(&Vs[kk][ty*4]);
            const float4 bb = *reinterpret_cast<const float4*>(&As[kk][tx*4]);
            const float ar[4] = {a.x, a.y, a.z, a.w};
            const float br[4] = {bb.x, bb.y, bb.z, bb.w};
            #pragma unroll
            for (int i = 0; i < 4; i++)
                #pragma unroll
                for (int j = 0; j < 4; j++)
                    acc[i][j] = fmaf(ar[i], br[j], acc[i][j]);
        }
    }

    #pragma unroll
    for (int i = 0; i < 4; i++) {
        float* op = O + (size_t)(c0 + ty * 4 + i) * NSP + n0 + tx * 4;
        #pragma unroll
        for (int j = 0; j < 4; j++) op[j] = acc[i][j];
    }
}

// ============================ launch ============================
extern "C" void kernel_launch(void* const* d_in, const int* in_sizes, int n_in,
                              void* d_out, int out_size)
{
    const float* x     = (const float*)d_in[0];
    const float* gamma = (const float*)d_in[1];
    const float* beta  = (const float*)d_in[2];
    const float* wq    = (const float*)d_in[3];
    const float* bq    = (const float*)d_in[4];
    const float* wk    = (const float*)d_in[5];
    const float* bk    = (const float*)d_in[6];
    const float* wv    = (const float*)d_in[7];
    const float* bv    = (const float*)d_in[8];
    const float* wo    = (const float*)d_in[9];
    const float* bo    = (const float*)d_in[10];
    float* out = (float*)d_out;

    float *p_hn, *p_q, *p_k, *p_v, *p_o;
    cudaGetSymbolAddress((void**)&p_hn, g_hn);
    cudaGetSymbolAddress((void**)&p_q,  g_q);
    cudaGetSymbolAddress((void**)&p_k,  g_k);
    cudaGetSymbolAddress((void**)&p_v,  g_v);
    cudaGetSymbolAddress((void**)&p_o,  g_o);

    groupnorm_kernel<<<BATCH * NGROUPS, 256>>>(x, gamma, beta);

    const dim3 gc(NSP / 64, CCH / 64, BATCH);     // (64, 8, 4)
    conv_gemm<<<gc, 256>>>(wq, p_hn, bq, nullptr, p_q);
    conv_gemm<<<gc, 256>>>(wk, p_hn, bk, nullptr, p_k);
    conv_gemm<<<gc, 256>>>(wv, p_hn, bv, nullptr, p_v);

    const dim3 gs(NSP / 64, NSP / 64, BATCH);     // (64, 64, 4)
    scores_gemm<<<gs, 256>>>();

    softmax_kernel<<<BATCH * NSP, 256>>>();       // 16384 rows

    av_gemm<<<gc, 256>>>();

    conv_gemm<<<gc, 256>>>(wo, p_o, bo, x, out);
}

// round 2
// speedup vs baseline: 3.6894x; 3.6894x over previous
#include <cuda_runtime.h>
#include <math.h>
#include <stdint.h>

#define BATCH   4
#define CCH     512
#define NSP     4096
#define NGROUPS 32
#define CPG     16

// -------- scratch (static device globals; allocation-free) --------
__device__ float g_hn[(size_t)BATCH * CCH * NSP];
__device__ float g_q [(size_t)BATCH * CCH * NSP];
__device__ float g_k [(size_t)BATCH * CCH * NSP];
__device__ float g_v [(size_t)BATCH * CCH * NSP];
__device__ float g_o [(size_t)BATCH * CCH * NSP];
__device__ float g_wr[(size_t)4 * CCH * CCH];
__device__ float g_attn[(size_t)BATCH * NSP * NSP];

// ---------------- helpers ----------------
__device__ __forceinline__ float tf32r(float x){
    uint32_t u; asm("cvt.rna.tf32.f32 %0, %1;" : "=r"(u) : "f"(x));
    return __uint_as_float(u);
}
__device__ __forceinline__ uint32_t f2u(float x){ return __float_as_uint(x); }

__device__ __forceinline__ void cpa16(float* dst, const float* src){
    uint32_t s = (uint32_t)__cvta_generic_to_shared(dst);
    asm volatile("cp.async.cg.shared.global [%0], [%1], 16;" :: "r"(s), "l"(src));
}
#define CP_COMMIT asm volatile("cp.async.commit_group;")
#define CP_WAIT(n) asm volatile("cp.async.wait_group %0;" :: "n"(n))

__device__ __forceinline__ void mma8(float* c, const uint32_t* a, const uint32_t* b){
    asm volatile(
      "mma.sync.aligned.m16n8k8.row.col.f32.tf32.tf32.f32 "
      "{%0,%1,%2,%3},{%4,%5,%6,%7},{%8,%9},{%0,%1,%2,%3};"
      : "+f"(c[0]), "+f"(c[1]), "+f"(c[2]), "+f"(c[3])
      : "r"(a[0]), "r"(a[1]), "r"(a[2]), "r"(a[3]), "r"(b[0]), "r"(b[1]));
}

// ============================ tf32 tensor-core GEMM ============================
// D[m][n] = scale * sum_k A[m][k]*B[k][n] (+bias[m]) (+res[m][n]); optional tf32
// rounding of outputs (inputs to downstream GEMMs).
// A_KM: A stored [K][M].  B_NK: B stored [N][K].
template<bool A_KM, bool B_NK>
__global__ void __launch_bounds__(256, 2) tgemm(
    const float* __restrict__ A, const float* __restrict__ B,
    const float* __restrict__ bias, const float* __restrict__ res,
    float* __restrict__ D, int M, int N, int K,
    size_t sA, size_t sB, size_t sD, float scale, int round_out)
{
    extern __shared__ float smem[];
    constexpr int A_FLOATS = A_KM ? 32*136 : 128*36;
    constexpr int B_FLOATS = B_NK ? 128*36 : 32*136;
    constexpr int BUF = A_FLOATS + B_FLOATS;

    const int tid = threadIdx.x, lane = tid & 31, wid = tid >> 5;
    const int g = lane >> 2, tig = lane & 3;
    const int wm = wid >> 2, wn = wid & 3;
    const int m0 = blockIdx.y * 128, n0 = blockIdx.x * 128;
    const int lda = A_KM ? M : K;
    const int ldb = B_NK ? K : N;

    A += (size_t)blockIdx.z * sA;
    B += (size_t)blockIdx.z * sB;
    D += (size_t)blockIdx.z * sD;
    const float* resp = res ? res + (size_t)blockIdx.z * sD : nullptr;

    const int NK = K >> 5;
    float acc[4][4][4];
    #pragma unroll
    for (int i = 0; i < 4; i++)
        #pragma unroll
        for (int j = 0; j < 4; j++)
            #pragma unroll
            for (int r = 0; r < 4; r++) acc[i][j][r] = 0.f;

    auto issue = [&](int ks){
        float* As = smem + (ks & 1) * BUF;
        float* Bs = As + A_FLOATS;
        if constexpr (A_KM) {
            #pragma unroll
            for (int it = 0; it < 4; it++){
                const int r = it*8 + (tid>>5), c = (tid & 31) * 4;
                cpa16(As + r*136 + c, A + (size_t)(ks*32 + r)*lda + m0 + c);
            }
        } else {
            #pragma unroll
            for (int it = 0; it < 4; it++){
                const int r = it*32 + (tid>>3), c = (tid & 7) * 4;
                cpa16(As + r*36 + c, A + (size_t)(m0 + r)*lda + ks*32 + c);
            }
        }
        if constexpr (B_NK) {
            #pragma unroll
            for (int it = 0; it < 4; it++){
                const int r = it*32 + (tid>>3), c = (tid & 7) * 4;
                cpa16(Bs + r*36 + c, B + (size_t)(n0 + r)*ldb + ks*32 + c);
            }
        } else {
            #pragma unroll
            for (int it = 0; it < 4; it++){
                const int r = it*8 + (tid>>5), c = (tid & 31) * 4;
                cpa16(Bs + r*136 + c, B + (size_t)(ks*32 + r)*ldb + n0 + c);
            }
        }
    };

    issue(0); CP_COMMIT;

    for (int ks = 0; ks < NK; ks++){
        if (ks + 1 < NK) { issue(ks + 1); CP_COMMIT; CP_WAIT(1); }
        else             { CP_WAIT(0); }
        __syncthreads();

        const float* As = smem + (ks & 1) * BUF;
        const float* Bs = As + A_FLOATS;
        #pragma unroll
        for (int kk8 = 0; kk8 < 4; kk8++){
            const int kk = kk8 * 8;
            uint32_t a[4][4], b[4][2];
            #pragma unroll
            for (int i = 0; i < 4; i++){
                const int mr = wm*64 + i*16 + g;
                if constexpr (A_KM) {
                    a[i][0] = f2u(As[(kk+tig  )*136 + mr    ]);
                    a[i][1] = f2u(As[(kk+tig  )*136 + mr + 8]);
                    a[i][2] = f2u(As[(kk+tig+4)*136 + mr    ]);
                    a[i][3] = f2u(As[(kk+tig+4)*136 + mr + 8]);
                } else {
                    a[i][0] = f2u(As[(mr    )*36 + kk+tig  ]);
                    a[i][1] = f2u(As[(mr + 8)*36 + kk+tig  ]);
                    a[i][2] = f2u(As[(mr    )*36 + kk+tig+4]);
                    a[i][3] = f2u(As[(mr + 8)*36 + kk+tig+4]);
                }
            }
            #pragma unroll
            for (int j = 0; j < 4; j++){
                const int nc = wn*32 + j*8 + g;
                if constexpr (B_NK) {
                    b[j][0] = f2u(Bs[nc*36 + kk+tig  ]);
                    b[j][1] = f2u(Bs[nc*36 + kk+tig+4]);
                } else {
                    b[j][0] = f2u(Bs[(kk+tig  )*136 + nc]);
                    b[j][1] = f2u(Bs[(kk+tig+4)*136 + nc]);
                }
            }
            #pragma unroll
            for (int i = 0; i < 4; i++)
                #pragma unroll
                for (int j = 0; j < 4; j++)
                    mma8(acc[i][j], a[i], b[j]);
        }
        __syncthreads();
    }

    #pragma unroll
    for (int i = 0; i < 4; i++){
        const int row = m0 + wm*64 + i*16 + g;
        float b0 = 0.f, b1 = 0.f;
        if (bias) { b0 = bias[row]; b1 = bias[row + 8]; }
        #pragma unroll
        for (int j = 0; j < 4; j++){
            const int col = n0 + wn*32 + j*8 + tig*2;
            float v0 = acc[i][j][0]*scale + b0;
            float v1 = acc[i][j][1]*scale + b0;
            float v2 = acc[i][j][2]*scale + b1;
            float v3 = acc[i][j][3]*scale + b1;
            if (resp){
                v0 += resp[(size_t)row*N + col];
                v1 += resp[(size_t)row*N + col + 1];
                v2 += resp[(size_t)(row+8)*N + col];
                v3 += resp[(size_t)(row+8)*N + col + 1];
            }
            if (round_out){
                v0 = tf32r(v0); v1 = tf32r(v1); v2 = tf32r(v2); v3 = tf32r(v3);
            }
            *reinterpret_cast<float2*>(D + (size_t)row*N + col)     = make_float2(v0, v1);
            *reinterpret_cast<float2*>(D + (size_t)(row+8)*N + col) = make_float2(v2, v3);
        }
    }
}

// ============================ weight rounding ============================
__global__ void round_copy(const float* __restrict__ src, float* __restrict__ dst, int n)
{
    int i = blockIdx.x * 256 + threadIdx.x;
    if (i < n) dst[i] = tf32r(src[i]);
}

// ============================ GroupNorm (tf32-rounded output) ============================
__global__ void __launch_bounds__(256) groupnorm_kernel(
    const float* __restrict__ x,
    const float* __restrict__ gamma,
    const float* __restrict__ beta)
{
    const int b = blockIdx.x >> 5;
    const int g = blockIdx.x & 31;
    const size_t base = ((size_t)b * CCH + (size_t)g * CPG) * NSP;
    const float4* xp = reinterpret_cast<const float4*>(x + base);
    float4*       hp = reinterpret_cast<float4*>(g_hn + base);
    const int nv = CPG * NSP / 4;

    float s = 0.f, ss = 0.f;
    for (int i = threadIdx.x; i < nv; i += 256) {
        float4 v = xp[i];
        s  += v.x + v.y + v.z + v.w;
        ss += v.x*v.x + v.y*v.y + v.z*v.z + v.w*v.w;
    }
    __shared__ float rs[256], rq[256];
    rs[threadIdx.x] = s; rq[threadIdx.x] = ss;
    __syncthreads();
    #pragma unroll
    for (int o = 128; o > 0; o >>= 1) {
        if (threadIdx.x < o) {
            rs[threadIdx.x] += rs[threadIdx.x + o];
            rq[threadIdx.x] += rq[threadIdx.x + o];
        }
        __syncthreads();
    }
    const float inv_n = 1.f / (float)(CPG * NSP);
    const float mean = rs[0] * inv_n;
    const float var  = rq[0] * inv_n - mean * mean;
    const float inv  = rsqrtf(var + 1e-6f);

    for (int i = threadIdx.x; i < nv; i += 256) {
        const int c = g * CPG + (i >> 10);
        const float ga = gamma[c] * inv;
        const float be = beta[c] - mean * ga;
        float4 v = xp[i];
        v.x = tf32r(v.x * ga + be);
        v.y = tf32r(v.y * ga + be);
        v.z = tf32r(v.z * ga + be);
        v.w = tf32r(v.w * ga + be);
        hp[i] = v;
    }
}

// ============================ softmax (tf32-rounded output) ============================
__global__ void __launch_bounds__(256) softmax_kernel()
{
    float* p = g_attn + (size_t)blockIdx.x * NSP;
    const int tid = threadIdx.x;

    float4 v[4];
    float mx = -3.4e38f;
    #pragma unroll
    for (int i = 0; i < 4; i++) {
        v[i] = reinterpret_cast<float4*>(p)[tid + i * 256];
        mx = fmaxf(mx, fmaxf(fmaxf(v[i].x, v[i].y), fmaxf(v[i].z, v[i].w)));
    }

    __shared__ float red[8];
    __shared__ float bval;
    #pragma unroll
    for (int o = 16; o > 0; o >>= 1) mx = fmaxf(mx, __shfl_xor_sync(0xffffffffu, mx, o));
    if ((tid & 31) == 0) red[tid >> 5] = mx;
    __syncthreads();
    if (tid < 8) {
        float m = red[tid];
        #pragma unroll
        for (int o = 4; o > 0; o >>= 1) m = fmaxf(m, __shfl_xor_sync(0xffu, m, o));
        if (tid == 0) bval = m;
    }
    __syncthreads();
    mx = bval;

    float sum = 0.f;
    #pragma unroll
    for (int i = 0; i < 4; i++) {
        v[i].x = expf(v[i].x - mx); v[i].y = expf(v[i].y - mx);
        v[i].z = expf(v[i].z - mx); v[i].w = expf(v[i].w - mx);
        sum += v[i].x + v[i].y + v[i].z + v[i].w;
    }
    #pragma unroll
    for (int o = 16; o > 0; o >>= 1) sum += __shfl_xor_sync(0xffffffffu, sum, o);
    __syncthreads();
    if ((tid & 31) == 0) red[tid >> 5] = sum;
    __syncthreads();
    if (tid < 8) {
        float s2 = red[tid];
        #pragma unroll
        for (int o = 4; o > 0; o >>= 1) s2 += __shfl_xor_sync(0xffu, s2, o);
        if (tid == 0) bval = s2;
    }
    __syncthreads();

    const float r = 1.f / bval;
    #pragma unroll
    for (int i = 0; i < 4; i++) {
        v[i].x = tf32r(v[i].x * r); v[i].y = tf32r(v[i].y * r);
        v[i].z = tf32r(v[i].z * r); v[i].w = tf32r(v[i].w * r);
        reinterpret_cast<float4*>(p)[tid + i * 256] = v[i];
    }
}

// ============================ launch ============================
extern "C" void kernel_launch(void* const* d_in, const int* in_sizes, int n_in,
                              void* d_out, int out_size)
{
    const float* x     = (const float*)d_in[0];
    const float* gamma = (const float*)d_in[1];
    const float* beta  = (const float*)d_in[2];
    const float* wq    = (const float*)d_in[3];
    const float* bq    = (const float*)d_in[4];
    const float* wk    = (const float*)d_in[5];
    const float* bk    = (const float*)d_in[6];
    const float* wv    = (const float*)d_in[7];
    const float* bv    = (const float*)d_in[8];
    const float* wo    = (const float*)d_in[9];
    const float* bo    = (const float*)d_in[10];
    float* out = (float*)d_out;

    float *p_hn, *p_q, *p_k, *p_v, *p_o, *p_wr, *p_attn;
    cudaGetSymbolAddress((void**)&p_hn,   g_hn);
    cudaGetSymbolAddress((void**)&p_q,    g_q);
    cudaGetSymbolAddress((void**)&p_k,    g_k);
    cudaGetSymbolAddress((void**)&p_v,    g_v);
    cudaGetSymbolAddress((void**)&p_o,    g_o);
    cudaGetSymbolAddress((void**)&p_wr,   g_wr);
    cudaGetSymbolAddress((void**)&p_attn, g_attn);

    const int SM_CONV   = 2 * (128*36 + 32*136) * 4;
    const int SM_SCORES = 2 * (32*136 + 32*136) * 4;
    const int SM_AV     = 2 * (128*36 + 128*36) * 4;
    cudaFuncSetAttribute(tgemm<false,false>, cudaFuncAttributeMaxDynamicSharedMemorySize, SM_CONV);
    cudaFuncSetAttribute(tgemm<true, false>, cudaFuncAttributeMaxDynamicSharedMemorySize, SM_SCORES);
    cudaFuncSetAttribute(tgemm<false,true >, cudaFuncAttributeMaxDynamicSharedMemorySize, SM_AV);

    const int WN = CCH * CCH;
    round_copy<<<(WN + 255)/256, 256>>>(wq, p_wr + 0*(size_t)WN, WN);
    round_copy<<<(WN + 255)/256, 256>>>(wk, p_wr + 1*(size_t)WN, WN);
    round_copy<<<(WN + 255)/256, 256>>>(wv, p_wr + 2*(size_t)WN, WN);
    round_copy<<<(WN + 255)/256, 256>>>(wo, p_wr + 3*(size_t)WN, WN);

    groupnorm_kernel<<<BATCH * NGROUPS, 256>>>(x, gamma, beta);

    const size_t sBC = (size_t)CCH * NSP;
    const size_t sAT = (size_t)NSP * NSP;

    const dim3 gc(NSP/128, CCH/128, BATCH);
    tgemm<false,false><<<gc, 256, SM_CONV>>>(p_wr + 0*(size_t)WN, p_hn, bq, nullptr,
                                             p_q, CCH, NSP, CCH, 0, sBC, sBC, 1.f, 1);
    tgemm<false,false><<<gc, 256, SM_CONV>>>(p_wr + 1*(size_t)WN, p_hn, bk, nullptr,
                                             p_k, CCH, NSP, CCH, 0, sBC, sBC, 1.f, 1);
    tgemm<false,false><<<gc, 256, SM_CONV>>>(p_wr + 2*(size_t)WN, p_hn, bv, nullptr,
                                             p_v, CCH, NSP, CCH, 0, sBC, sBC, 1.f, 1);

    const dim3 gs(NSP/128, NSP/128, BATCH);
    tgemm<true,false><<<gs, 256, SM_SCORES>>>(p_q, p_k, nullptr, nullptr,
                                              p_attn, NSP, NSP, CCH, sBC, sBC, sAT,
                                              0.04419417382415922f, 0);

    softmax_kernel<<<BATCH * NSP, 256>>>();

    tgemm<false,true><<<gc, 256, SM_AV>>>(p_v, p_attn, nullptr, nullptr,
                                          p_o, CCH, NSP, NSP, sBC, sAT, sBC, 1.f, 1);

    tgemm<false,false><<<gc, 256, SM_CONV>>>(p_wr + 3*(size_t)WN, p_o, bo, x,
                                             out, CCH, NSP, CCH, 0, sBC, sBC, 1.f, 0);
}

// round 5
// speedup vs baseline: 5.5340x; 1.5000x over previous
#include <cuda_runtime.h>
#include <cuda_fp16.h>
#include <math.h>
#include <stdint.h>

#define BATCH 4
#define CCH   512
#define NSP   4096

// ---------------- scratch (static device globals; allocation-free) ----------------
__device__ unsigned short gh_hnT [(size_t)BATCH * NSP * CCH];   // [b][n][c] fp16
__device__ unsigned short gh_qT  [(size_t)BATCH * NSP * CCH];   // [b][n][c]
__device__ unsigned short gh_kT  [(size_t)BATCH * NSP * CCH];   // [b][n][c]
__device__ unsigned short gh_v   [(size_t)BATCH * CCH * NSP];   // [b][c][n]
__device__ unsigned short gh_oT  [(size_t)BATCH * NSP * CCH];   // [b][n][c]
__device__ unsigned short gh_w   [(size_t)4 * CCH * CCH];       // wq,wk,wv,wo fp16
__device__ float          g_attn [(size_t)BATCH * NSP * NSP];   // fp32 scores
__device__ unsigned short gh_attn[(size_t)BATCH * NSP * NSP];   // fp16 attn
__device__ float g_ga[BATCH * CCH];
__device__ float g_be[BATCH * CCH];

// ---------------- helpers ----------------
__device__ __forceinline__ void cpa16(void* dst, const void* src){
    uint32_t s = (uint32_t)__cvta_generic_to_shared(dst);
    asm volatile("cp.async.cg.shared.global [%0], [%1], 16;" :: "r"(s), "l"(src));
}
#define CP_COMMIT() asm volatile("cp.async.commit_group;")

__device__ __forceinline__ void mma16(float* c, const uint32_t* a, const uint32_t* b){
    asm volatile(
      "mma.sync.aligned.m16n8k16.row.col.f32.f16.f16.f32 "
      "{%0,%1,%2,%3},{%4,%5,%6,%7},{%8,%9},{%0,%1,%2,%3};"
      : "+f"(c[0]), "+f"(c[1]), "+f"(c[2]), "+f"(c[3])
      : "r"(a[0]), "r"(a[1]), "r"(a[2]), "r"(a[3]), "r"(b[0]), "r"(b[1]));
}

__device__ __forceinline__ uint32_t pack2(float x, float y){
    __half2 h = __floats2half2_rn(x, y);
    return *reinterpret_cast<uint32_t*>(&h);
}

// ============================ fp16 tensor-core GEMM ============================
// D[m][n] = scale * sum_k A[m][k] * B[n][k]   (A,B fp16 K-major)
// bias_col==0: bias indexed by row (may be null). bias_col==1: bias indexed by col.
// out_f32: 1 -> fp32 output (+optional res, fp32, same layout); 0 -> fp16 output.
__global__ void __launch_bounds__(256, 2) hgemm(
    const __half* __restrict__ A, const __half* __restrict__ B,
    const float* __restrict__ bias, const float* __restrict__ res,
    void* __restrict__ D,
    int K, int ldA, int ldB, int ldD,
    size_t sA, size_t sB, size_t sD,
    float scale, int bias_col, int out_f32)
{
    __shared__ __half sm[2][2][128][40];   // [buf][A/B][row][k] — 40-half rows: conflict-free

    const int tid = threadIdx.x, lane = tid & 31, wid = tid >> 5;
    const int g = lane >> 2, tig = lane & 3;
    const int wm = wid >> 2, wn = wid & 3;         // 2 x 4 warp grid
    const int m0 = blockIdx.y * 128, n0 = blockIdx.x * 128;
    const int bz = blockIdx.z;

    const __half* Ag = A + (size_t)bz * sA;
    const __half* Bg = B + (size_t)bz * sB;

    float acc[4][4][4];
    #pragma unroll
    for (int i = 0; i < 4; i++)
        #pragma unroll
        for (int j = 0; j < 4; j++)
            #pragma unroll
            for (int r = 0; r < 4; r++) acc[i][j][r] = 0.f;

    const int NK = K >> 5;

    auto stage = [&](int ks){
        const int bf = ks & 1;
        #pragma unroll
        for (int it = 0; it < 2; it++){
            const int idx = it * 256 + tid;
            const int r = idx >> 2, c = (idx & 3) * 8;
            cpa16(&sm[bf][0][r][c], Ag + (size_t)(m0 + r) * ldA + ks * 32 + c);
            cpa16(&sm[bf][1][r][c], Bg + (size_t)(n0 + r) * ldB + ks * 32 + c);
        }
        CP_COMMIT();
    };

    stage(0);

    for (int ks = 0; ks < NK; ks++){
        if (ks + 1 < NK) { stage(ks + 1); asm volatile("cp.async.wait_group 1;"); }
        else             { asm volatile("cp.async.wait_group 0;"); }
        __syncthreads();

        const int bf = ks & 1;
        #pragma unroll
        for (int kk = 0; kk < 32; kk += 16){
            uint32_t a[4][4], b[4][2];
            #pragma unroll
            for (int mi = 0; mi < 4; mi++){
                const int mr = wm * 64 + mi * 16 + g;
                a[mi][0] = *reinterpret_cast<const uint32_t*>(&sm[bf][0][mr    ][kk + tig*2    ]);
                a[mi][1] = *reinterpret_cast<const uint32_t*>(&sm[bf][0][mr + 8][kk + tig*2    ]);
                a[mi][2] = *reinterpret_cast<const uint32_t*>(&sm[bf][0][mr    ][kk + tig*2 + 8]);
                a[mi][3] = *reinterpret_cast<const uint32_t*>(&sm[bf][0][mr + 8][kk + tig*2 + 8]);
            }
            #pragma unroll
            for (int nj = 0; nj < 4; nj++){
                const int nc = wn * 32 + nj * 8 + g;
                b[nj][0] = *reinterpret_cast<const uint32_t*>(&sm[bf][1][nc][kk + tig*2    ]);
                b[nj][1] = *reinterpret_cast<const uint32_t*>(&sm[bf][1][nc][kk + tig*2 + 8]);
            }
            #pragma unroll
            for (int mi = 0; mi < 4; mi++)
                #pragma unroll
                for (int nj = 0; nj < 4; nj++)
                    mma16(acc[mi][nj], a[mi], b[nj]);
        }
        __syncthreads();
    }

    // ---------------- epilogue ----------------
    #pragma unroll
    for (int mi = 0; mi < 4; mi++){
        const int r0 = m0 + wm * 64 + mi * 16 + g;
        float br0 = 0.f, br1 = 0.f;
        if (bias && !bias_col){ br0 = bias[r0]; br1 = bias[r0 + 8]; }
        #pragma unroll
        for (int nj = 0; nj < 4; nj++){
            const int col = n0 + wn * 32 + nj * 8 + tig * 2;
            float v0 = acc[mi][nj][0] * scale;
            float v1 = acc[mi][nj][1] * scale;
            float v2 = acc[mi][nj][2] * scale;
            float v3 = acc[mi][nj][3] * scale;
            if (bias){
                if (bias_col){
                    const float bc0 = bias[col], bc1 = bias[col + 1];
                    v0 += bc0; v1 += bc1; v2 += bc0; v3 += bc1;
                } else {
                    v0 += br0; v1 += br0; v2 += br1; v3 += br1;
                }
            }
            if (out_f32){
                float* o = (float*)D + (size_t)bz * sD;
                if (res){
                    const float* rp = res + (size_t)bz * sD;
                    v0 += rp[(size_t)r0 * ldD + col];
                    v1 += rp[(size_t)r0 * ldD + col + 1];
                    v2 += rp[(size_t)(r0 + 8) * ldD + col];
                    v3 += rp[(size_t)(r0 + 8) * ldD + col + 1];
                }
                *reinterpret_cast<float2*>(o + (size_t)r0 * ldD + col)       = make_float2(v0, v1);
                *reinterpret_cast<float2*>(o + (size_t)(r0 + 8) * ldD + col) = make_float2(v2, v3);
            } else {
                __half* o = (__half*)D + (size_t)bz * sD;
                *reinterpret_cast<uint32_t*>(o + (size_t)r0 * ldD + col)       = pack2(v0, v1);
                *reinterpret_cast<uint32_t*>(o + (size_t)(r0 + 8) * ldD + col) = pack2(v2, v3);
            }
        }
    }
}

// ============================ GroupNorm stats ============================
__global__ void __launch_bounds__(256) gn_stats(
    const float* __restrict__ x,
    const float* __restrict__ gamma,
    const float* __restrict__ beta)
{
    const int b = blockIdx.x >> 5;
    const int g = blockIdx.x & 31;
    const size_t base = ((size_t)b * CCH + (size_t)g * 16) * NSP;
    const float4* xp = reinterpret_cast<const float4*>(x + base);
    const int nv = 16 * NSP / 4;

    float s = 0.f, ss = 0.f;
    for (int i = threadIdx.x; i < nv; i += 256){
        float4 v = xp[i];
        s  += v.x + v.y + v.z + v.w;
        ss += v.x*v.x + v.y*v.y + v.z*v.z + v.w*v.w;
    }
    __shared__ float rs[256], rq[256];
    rs[threadIdx.x] = s; rq[threadIdx.x] = ss;
    __syncthreads();
    #pragma unroll
    for (int o = 128; o > 0; o >>= 1){
        if (threadIdx.x < o){ rs[threadIdx.x] += rs[threadIdx.x + o]; rq[threadIdx.x] += rq[threadIdx.x + o]; }
        __syncthreads();
    }
    if (threadIdx.x < 16){
        const float inv_n = 1.f / (float)(16 * NSP);
        const float mean = rs[0] * inv_n;
        const float var  = rq[0] * inv_n - mean * mean;
        const float inv  = rsqrtf(var + 1e-6f);
        const int c = g * 16 + threadIdx.x;
        const float ga = gamma[c] * inv;
        g_ga[b * CCH + c] = ga;
        g_be[b * CCH + c] = beta[c] - mean * ga;
    }
}

// ============================ normalize + transpose -> hnT fp16 ============================
__global__ void __launch_bounds__(256) norm_transpose(const float* __restrict__ x)
{
    __shared__ float t[64][65];
    const int b  = blockIdx.z;
    const int n0 = blockIdx.x * 64;
    const int c0 = blockIdx.y * 64;
    const int tid = threadIdx.x;
    const int r = tid >> 2, cs = (tid & 3) * 16;

    const float ga = g_ga[b * CCH + c0 + r];
    const float be = g_be[b * CCH + c0 + r];
    const float4* src = reinterpret_cast<const float4*>(
        x + (size_t)b * CCH * NSP + (size_t)(c0 + r) * NSP + n0 + cs);
    #pragma unroll
    for (int i = 0; i < 4; i++){
        float4 v = src[i];
        t[r][cs + 4*i + 0] = v.x * ga + be;
        t[r][cs + 4*i + 1] = v.y * ga + be;
        t[r][cs + 4*i + 2] = v.z * ga + be;
        t[r][cs + 4*i + 3] = v.w * ga + be;
    }
    __syncthreads();

    __half* dst = reinterpret_cast<__half*>(gh_hnT)
        + (size_t)b * NSP * CCH + (size_t)(n0 + r) * CCH + c0 + cs;
    uint32_t pk[8];
    #pragma unroll
    for (int j = 0; j < 8; j++)
        pk[j] = pack2(t[cs + 2*j][r], t[cs + 2*j + 1][r]);
    reinterpret_cast<uint4*>(dst)[0] = make_uint4(pk[0], pk[1], pk[2], pk[3]);
    reinterpret_cast<uint4*>(dst)[1] = make_uint4(pk[4], pk[5], pk[6], pk[7]);
}

// ============================ weight fp32 -> fp16 ============================
__global__ void conv_w(const float* __restrict__ w, unsigned short* __restrict__ dst, int n)
{
    int i = blockIdx.x * 256 + threadIdx.x;
    if (i < n){
        __half h = __float2half_rn(w[i]);
        dst[i] = *reinterpret_cast<unsigned short*>(&h);
    }
}

// ============================ softmax (fp32 in, fp16 out) ============================
__global__ void __launch_bounds__(256) softmax_kernel()
{
    const float* p = g_attn + (size_t)blockIdx.x * NSP;
    uint2* ob = reinterpret_cast<uint2*>(gh_attn) + (size_t)blockIdx.x * (NSP / 4);
    const int tid = threadIdx.x;

    float4 v[4];
    float mx = -3.4e38f;
    #pragma unroll
    for (int i = 0; i < 4; i++){
        v[i] = reinterpret_cast<const float4*>(p)[tid + i * 256];
        mx = fmaxf(mx, fmaxf(fmaxf(v[i].x, v[i].y), fmaxf(v[i].z, v[i].w)));
    }

    __shared__ float red[8];
    __shared__ float bval;
    #pragma unroll
    for (int o = 16; o > 0; o >>= 1) mx = fmaxf(mx, __shfl_xor_sync(0xffffffffu, mx, o));
    if ((tid & 31) == 0) red[tid >> 5] = mx;
    __syncthreads();
    if (tid < 8){
        float m = red[tid];
        #pragma unroll
        for (int o = 4; o > 0; o >>= 1) m = fmaxf(m, __shfl_xor_sync(0xffu, m, o));
        if (tid == 0) bval = m;
    }
    __syncthreads();
    mx = bval;

    float sum = 0.f;
    #pragma unroll
    for (int i = 0; i < 4; i++){
        v[i].x = expf(v[i].x - mx); v[i].y = expf(v[i].y - mx);
        v[i].z = expf(v[i].z - mx); v[i].w = expf(v[i].w - mx);
        sum += v[i].x + v[i].y + v[i].z + v[i].w;
    }
    #pragma unroll
    for (int o = 16; o > 0; o >>= 1) sum += __shfl_xor_sync(0xffffffffu, sum, o);
    __syncthreads();
    if ((tid & 31) == 0) red[tid >> 5] = sum;
    __syncthreads();
    if (tid < 8){
        float s2 = red[tid];
        #pragma unroll
        for (int o = 4; o > 0; o >>= 1) s2 += __shfl_xor_sync(0xffu, s2, o);
        if (tid == 0) bval = s2;
    }
    __syncthreads();

    const float r = 1.f / bval;
    #pragma unroll
    for (int i = 0; i < 4; i++)
        ob[tid + i * 256] = make_uint2(pack2(v[i].x * r, v[i].y * r),
                                       pack2(v[i].z * r, v[i].w * r));
}

// ============================ launch ============================
extern "C" void kernel_launch(void* const* d_in, const int* in_sizes, int n_in,
                              void* d_out, int out_size)
{
    const float* x     = (const float*)d_in[0];
    const float* gamma = (const float*)d_in[1];
    const float* beta  = (const float*)d_in[2];
    const float* wq    = (const float*)d_in[3];
    const float* bq    = (const float*)d_in[4];
    const float* wk    = (const float*)d_in[5];
    const float* bk    = (const float*)d_in[6];
    const float* wv    = (const float*)d_in[7];
    const float* bv    = (const float*)d_in[8];
    const float* wo    = (const float*)d_in[9];
    const float* bo    = (const float*)d_in[10];
    float* out = (float*)d_out;

    unsigned short *p_hnT, *p_qT, *p_kT, *p_v, *p_oT, *p_w, *p_attnh;
    float *p_attn;
    cudaGetSymbolAddress((void**)&p_hnT,   gh_hnT);
    cudaGetSymbolAddress((void**)&p_qT,    gh_qT);
    cudaGetSymbolAddress((void**)&p_kT,    gh_kT);
    cudaGetSymbolAddress((void**)&p_v,     gh_v);
    cudaGetSymbolAddress((void**)&p_oT,    gh_oT);
    cudaGetSymbolAddress((void**)&p_w,     gh_w);
    cudaGetSymbolAddress((void**)&p_attn,  g_attn);
    cudaGetSymbolAddress((void**)&p_attnh, gh_attn);

    const int WN = CCH * CCH;
    conv_w<<<(WN + 255)/256, 256>>>(wq, p_w + 0*(size_t)WN, WN);
    conv_w<<<(WN + 255)/256, 256>>>(wk, p_w + 1*(size_t)WN, WN);
    conv_w<<<(WN + 255)/256, 256>>>(wv, p_w + 2*(size_t)WN, WN);
    conv_w<<<(WN + 255)/256, 256>>>(wo, p_w + 3*(size_t)WN, WN);

    gn_stats<<<BATCH * 32, 256>>>(x, gamma, beta);
    norm_transpose<<<dim3(NSP/64, CCH/64, BATCH), 256>>>(x);

    const size_t sNC = (size_t)NSP * CCH;
    const size_t sAT = (size_t)NSP * NSP;
    const __half* hw   = (const __half*)p_w;
    const __half* hhnT = (const __half*)p_hnT;

    // qT[n][co] = sum_c hnT[n][c] * Wq[co][c] + bq[co]   (M=4096, N=512, K=512)
    const dim3 g_nq(CCH/128, NSP/128, BATCH);     // (4, 32, 4)
    hgemm<<<g_nq, 256>>>(hhnT, hw + 0*(size_t)WN, bq, nullptr, p_qT,
                         CCH, CCH, CCH, CCH, sNC, 0, sNC, 1.f, 1, 0);
    hgemm<<<g_nq, 256>>>(hhnT, hw + 1*(size_t)WN, bk, nullptr, p_kT,
                         CCH, CCH, CCH, CCH, sNC, 0, sNC, 1.f, 1, 0);

    // v[co][n] = sum_c Wv[co][c] * hnT[n][c] + bv[co]    (M=512, N=4096, K=512)
    const dim3 g_cn(NSP/128, CCH/128, BATCH);     // (32, 4, 4)
    hgemm<<<g_cn, 256>>>(hw + 2*(size_t)WN, hhnT, bv, nullptr, p_v,
                         CCH, CCH, CCH, NSP, 0, sNC, sNC, 1.f, 0, 0);

    // scores[nq][nk] = scale * sum_c qT[nq][c] * kT[nk][c]   (M=N=4096, K=512), fp32 out
    const dim3 g_ss(NSP/128, NSP/128, BATCH);     // (32, 32, 4)
    hgemm<<<g_ss, 256>>>((const __half*)p_qT, (const __half*)p_kT, nullptr, nullptr, p_attn,
                         CCH, CCH, CCH, NSP, sNC, sNC, sAT, 0.04419417382415922f, 0, 1);

    softmax_kernel<<<BATCH * NSP, 256>>>();

    // oT[nq][c] = sum_m attn[nq][m] * v[c][m]   (M=4096, N=512, K=4096)
    hgemm<<<g_nq, 256>>>((const __half*)p_attnh, (const __half*)p_v, nullptr, nullptr, p_oT,
                         NSP, NSP, NSP, CCH, sAT, sNC, sNC, 1.f, 0, 0);

    // out[co][n] = sum_c Wo[co][c] * oT[n][c] + bo[co] + x[co][n]  (M=512, N=4096, K=512), fp32 out
    hgemm<<<g_cn, 256>>>(hw + 3*(size_t)WN, (const __half*)p_oT, bo, x, out,
                         CCH, CCH, CCH, NSP, 0, sNC, (size_t)CCH * NSP, 1.f, 0, 1);
}

// round 6
// speedup vs baseline: 6.9952x; 1.2640x over previous
#include <cuda_runtime.h>
#include <cuda_fp16.h>
#include <math.h>
#include <stdint.h>

#define BATCH 4
#define CCH   512
#define NSP   4096

// ---------------- scratch (static device globals; allocation-free) ----------------
__device__ unsigned short gh_hnT [(size_t)BATCH * NSP * CCH];   // [b][n][c] fp16
__device__ unsigned short gh_qT  [(size_t)BATCH * NSP * CCH];   // [b][n][c]
__device__ unsigned short gh_kT  [(size_t)BATCH * NSP * CCH];   // [b][n][c]
__device__ unsigned short gh_v   [(size_t)BATCH * CCH * NSP];   // [b][c][n]
__device__ unsigned short gh_oT  [(size_t)BATCH * NSP * CCH];   // [b][n][c]
__device__ unsigned short gh_w   [(size_t)4 * CCH * CCH];       // wq,wk,wv,wo fp16
__device__ unsigned short gh_attn[(size_t)BATCH * NSP * NSP];   // fp16 scores/attn
__device__ float g_ga[BATCH * CCH];
__device__ float g_be[BATCH * CCH];

// ---------------- helpers ----------------
__device__ __forceinline__ void cpa16(void* dst, const void* src){
    uint32_t s = (uint32_t)__cvta_generic_to_shared(dst);
    asm volatile("cp.async.cg.shared.global [%0], [%1], 16;" :: "r"(s), "l"(src));
}
#define CP_COMMIT() asm volatile("cp.async.commit_group;")

__device__ __forceinline__ void ldm_x4(uint32_t* r, const void* p){
    uint32_t a = (uint32_t)__cvta_generic_to_shared(p);
    asm volatile("ldmatrix.sync.aligned.m8n8.x4.shared.b16 {%0,%1,%2,%3}, [%4];"
        : "=r"(r[0]), "=r"(r[1]), "=r"(r[2]), "=r"(r[3]) : "r"(a));
}

__device__ __forceinline__ void mma16(float* c, const uint32_t* a, const uint32_t* b){
    asm volatile(
      "mma.sync.aligned.m16n8k16.row.col.f32.f16.f16.f32 "
      "{%0,%1,%2,%3},{%4,%5,%6,%7},{%8,%9},{%0,%1,%2,%3};"
      : "+f"(c[0]), "+f"(c[1]), "+f"(c[2]), "+f"(c[3])
      : "r"(a[0]), "r"(a[1]), "r"(a[2]), "r"(a[3]), "r"(b[0]), "r"(b[1]));
}

__device__ __forceinline__ uint32_t pack2(float x, float y){
    __half2 h = __floats2half2_rn(x, y);
    return *reinterpret_cast<uint32_t*>(&h);
}

// ============================ fp16 tensor-core GEMM (ldmatrix, BK=64) ============================
// D[m][n] = scale * sum_k A[m][k] * B[n][k]   (A,B fp16 K-major)
// bias_col==0: bias per row; ==1: bias per col (bias may be null).
// out_f32: 1 -> fp32 out (+optional fp32 res); 0 -> fp16 out.
#define LDS_H 72                         // padded row stride in halfs (144 B)
#define MAT_H (128 * LDS_H)              // one 128-row tile
#define BUF_H (2 * MAT_H)                // A + B
#define SMEM_BYTES (2 * BUF_H * 2)       // double-buffered, 73728 B

__global__ void __launch_bounds__(256, 2) hgemm(
    const __half* __restrict__ A, const __half* __restrict__ B,
    const float* __restrict__ bias, const float* __restrict__ res,
    void* __restrict__ D,
    int K, int ldA, int ldB, int ldD,
    size_t sA, size_t sB, size_t sD,
    float scale, int bias_col, int out_f32)
{
    extern __shared__ __half smh[];

    const int tid = threadIdx.x, lane = tid & 31, wid = tid >> 5;
    const int g = lane >> 2, tig = lane & 3;
    const int wm = wid >> 2, wn = wid & 3;         // 2 x 4 warp grid
    const int m0 = blockIdx.y * 128, n0 = blockIdx.x * 128;
    const int bz = blockIdx.z;

    const __half* Ag = A + (size_t)bz * sA;
    const __half* Bg = B + (size_t)bz * sB;

    float acc[4][4][4];
    #pragma unroll
    for (int i = 0; i < 4; i++)
        #pragma unroll
        for (int j = 0; j < 4; j++)
            #pragma unroll
            for (int r = 0; r < 4; r++) acc[i][j][r] = 0.f;

    const int NK = K >> 6;

    auto stage = [&](int ks){
        __half* Asm = smh + (ks & 1) * BUF_H;
        __half* Bsm = Asm + MAT_H;
        #pragma unroll
        for (int it = 0; it < 4; it++){
            const int idx = it * 256 + tid;
            const int r = idx >> 3, c = (idx & 7) * 8;
            cpa16(Asm + r * LDS_H + c, Ag + (size_t)(m0 + r) * ldA + ks * 64 + c);
            cpa16(Bsm + r * LDS_H + c, Bg + (size_t)(n0 + r) * ldB + ks * 64 + c);
        }
        CP_COMMIT();
    };

    stage(0);

    // ldmatrix lane addressing (constant across kk except column offset)
    const int a_row = (lane & 15);            // + wm*64 + mi*16
    const int a_koff = (lane >> 4) * 8;       // 0 or 8
    const int b_row = ((lane >> 4) << 3) + (lane & 7);   // + wn*32 + pj*16
    const int b_koff = ((lane >> 3) & 1) * 8;

    for (int ks = 0; ks < NK; ks++){
        if (ks + 1 < NK) { stage(ks + 1); asm volatile("cp.async.wait_group 1;"); }
        else             { asm volatile("cp.async.wait_group 0;"); }
        __syncthreads();

        const __half* Asm = smh + (ks & 1) * BUF_H;
        const __half* Bsm = Asm + MAT_H;

        #pragma unroll
        for (int kk = 0; kk < 64; kk += 16){
            uint32_t a[4][4], b[4][2];
            #pragma unroll
            for (int mi = 0; mi < 4; mi++)
                ldm_x4(a[mi], Asm + (wm*64 + mi*16 + a_row) * LDS_H + kk + a_koff);
            #pragma unroll
            for (int pj = 0; pj < 2; pj++){
                uint32_t t4[4];
                ldm_x4(t4, Bsm + (wn*32 + pj*16 + b_row) * LDS_H + kk + b_koff);
                b[2*pj  ][0] = t4[0]; b[2*pj  ][1] = t4[1];
                b[2*pj+1][0] = t4[2]; b[2*pj+1][1] = t4[3];
            }
            #pragma unroll
            for (int mi = 0; mi < 4; mi++)
                #pragma unroll
                for (int nj = 0; nj < 4; nj++)
                    mma16(acc[mi][nj], a[mi], b[nj]);
        }
        __syncthreads();
    }

    // ---------------- epilogue ----------------
    #pragma unroll
    for (int mi = 0; mi < 4; mi++){
        const int r0 = m0 + wm * 64 + mi * 16 + g;
        float br0 = 0.f, br1 = 0.f;
        if (bias && !bias_col){ br0 = bias[r0]; br1 = bias[r0 + 8]; }
        #pragma unroll
        for (int nj = 0; nj < 4; nj++){
            const int col = n0 + wn * 32 + nj * 8 + tig * 2;
            float v0 = acc[mi][nj][0] * scale;
            float v1 = acc[mi][nj][1] * scale;
            float v2 = acc[mi][nj][2] * scale;
            float v3 = acc[mi][nj][3] * scale;
            if (bias){
                if (bias_col){
                    const float bc0 = bias[col], bc1 = bias[col + 1];
                    v0 += bc0; v1 += bc1; v2 += bc0; v3 += bc1;
                } else {
                    v0 += br0; v1 += br0; v2 += br1; v3 += br1;
                }
            }
            if (out_f32){
                float* o = (float*)D + (size_t)bz * sD;
                if (res){
                    const float* rp = res + (size_t)bz * sD;
                    v0 += rp[(size_t)r0 * ldD + col];
                    v1 += rp[(size_t)r0 * ldD + col + 1];
                    v2 += rp[(size_t)(r0 + 8) * ldD + col];
                    v3 += rp[(size_t)(r0 + 8) * ldD + col + 1];
                }
                *reinterpret_cast<float2*>(o + (size_t)r0 * ldD + col)       = make_float2(v0, v1);
                *reinterpret_cast<float2*>(o + (size_t)(r0 + 8) * ldD + col) = make_float2(v2, v3);
            } else {
                __half* o = (__half*)D + (size_t)bz * sD;
                *reinterpret_cast<uint32_t*>(o + (size_t)r0 * ldD + col)       = pack2(v0, v1);
                *reinterpret_cast<uint32_t*>(o + (size_t)(r0 + 8) * ldD + col) = pack2(v2, v3);
            }
        }
    }
}

// ============================ GroupNorm stats ============================
__global__ void __launch_bounds__(256) gn_stats(
    const float* __restrict__ x,
    const float* __restrict__ gamma,
    const float* __restrict__ beta)
{
    const int b = blockIdx.x >> 5;
    const int g = blockIdx.x & 31;
    const size_t base = ((size_t)b * CCH + (size_t)g * 16) * NSP;
    const float4* xp = reinterpret_cast<const float4*>(x + base);
    const int nv = 16 * NSP / 4;

    float s = 0.f, ss = 0.f;
    for (int i = threadIdx.x; i < nv; i += 256){
        float4 v = xp[i];
        s  += v.x + v.y + v.z + v.w;
        ss += v.x*v.x + v.y*v.y + v.z*v.z + v.w*v.w;
    }
    __shared__ float rs[256], rq[256];
    rs[threadIdx.x] = s; rq[threadIdx.x] = ss;
    __syncthreads();
    #pragma unroll
    for (int o = 128; o > 0; o >>= 1){
        if (threadIdx.x < o){ rs[threadIdx.x] += rs[threadIdx.x + o]; rq[threadIdx.x] += rq[threadIdx.x + o]; }
        __syncthreads();
    }
    if (threadIdx.x < 16){
        const float inv_n = 1.f / (float)(16 * NSP);
        const float mean = rs[0] * inv_n;
        const float var  = rq[0] * inv_n - mean * mean;
        const float inv  = rsqrtf(var + 1e-6f);
        const int c = g * 16 + threadIdx.x;
        const float ga = gamma[c] * inv;
        g_ga[b * CCH + c] = ga;
        g_be[b * CCH + c] = beta[c] - mean * ga;
    }
}

// ============================ normalize + transpose -> hnT fp16 ============================
__global__ void __launch_bounds__(256) norm_transpose(const float* __restrict__ x)
{
    __shared__ float t[64][65];
    const int b  = blockIdx.z;
    const int n0 = blockIdx.x * 64;
    const int c0 = blockIdx.y * 64;
    const int tid = threadIdx.x;
    const int r = tid >> 2, cs = (tid & 3) * 16;

    const float ga = g_ga[b * CCH + c0 + r];
    const float be = g_be[b * CCH + c0 + r];
    const float4* src = reinterpret_cast<const float4*>(
        x + (size_t)b * CCH * NSP + (size_t)(c0 + r) * NSP + n0 + cs);
    #pragma unroll
    for (int i = 0; i < 4; i++){
        float4 v = src[i];
        t[r][cs + 4*i + 0] = v.x * ga + be;
        t[r][cs + 4*i + 1] = v.y * ga + be;
        t[r][cs + 4*i + 2] = v.z * ga + be;
        t[r][cs + 4*i + 3] = v.w * ga + be;
    }
    __syncthreads();

    __half* dst = reinterpret_cast<__half*>(gh_hnT)
        + (size_t)b * NSP * CCH + (size_t)(n0 + r) * CCH + c0 + cs;
    uint32_t pk[8];
    #pragma unroll
    for (int j = 0; j < 8; j++)
        pk[j] = pack2(t[cs + 2*j][r], t[cs + 2*j + 1][r]);
    reinterpret_cast<uint4*>(dst)[0] = make_uint4(pk[0], pk[1], pk[2], pk[3]);
    reinterpret_cast<uint4*>(dst)[1] = make_uint4(pk[4], pk[5], pk[6], pk[7]);
}

// ============================ weight fp32 -> fp16 ============================
__global__ void conv_w(const float* __restrict__ w, unsigned short* __restrict__ dst, int n)
{
    int i = blockIdx.x * 256 + threadIdx.x;
    if (i < n){
        __half h = __float2half_rn(w[i]);
        dst[i] = *reinterpret_cast<unsigned short*>(&h);
    }
}

// ============================ softmax (fp16 in-place) ============================
__global__ void __launch_bounds__(256) softmax_h()
{
    uint4* p = reinterpret_cast<uint4*>(gh_attn) + (size_t)blockIdx.x * (NSP / 8);
    const int tid = threadIdx.x;

    uint4 raw[2];
    float f[16];
    float mx = -3.4e38f;
    #pragma unroll
    for (int i = 0; i < 2; i++){
        raw[i] = p[tid + i * 256];
        const uint32_t* w = reinterpret_cast<const uint32_t*>(&raw[i]);
        #pragma unroll
        for (int j = 0; j < 4; j++){
            float2 v = __half22float2(*reinterpret_cast<const __half2*>(&w[j]));
            f[i*8 + 2*j]     = v.x;
            f[i*8 + 2*j + 1] = v.y;
            mx = fmaxf(mx, fmaxf(v.x, v.y));
        }
    }

    __shared__ float red[8];
    __shared__ float bval;
    #pragma unroll
    for (int o = 16; o > 0; o >>= 1) mx = fmaxf(mx, __shfl_xor_sync(0xffffffffu, mx, o));
    if ((tid & 31) == 0) red[tid >> 5] = mx;
    __syncthreads();
    if (tid < 8){
        float m = red[tid];
        #pragma unroll
        for (int o = 4; o > 0; o >>= 1) m = fmaxf(m, __shfl_xor_sync(0xffu, m, o));
        if (tid == 0) bval = m;
    }
    __syncthreads();
    mx = bval;

    float sum = 0.f;
    #pragma unroll
    for (int i = 0; i < 16; i++){ f[i] = expf(f[i] - mx); sum += f[i]; }
    #pragma unroll
    for (int o = 16; o > 0; o >>= 1) sum += __shfl_xor_sync(0xffffffffu, sum, o);
    __syncthreads();
    if ((tid & 31) == 0) red[tid >> 5] = sum;
    __syncthreads();
    if (tid < 8){
        float s2 = red[tid];
        #pragma unroll
        for (int o = 4; o > 0; o >>= 1) s2 += __shfl_xor_sync(0xffu, s2, o);
        if (tid == 0) bval = s2;
    }
    __syncthreads();

    const float r = 1.f / bval;
    #pragma unroll
    for (int i = 0; i < 2; i++){
        uint4 o;
        o.x = pack2(f[i*8+0]*r, f[i*8+1]*r);
        o.y = pack2(f[i*8+2]*r, f[i*8+3]*r);
        o.z = pack2(f[i*8+4]*r, f[i*8+5]*r);
        o.w = pack2(f[i*8+6]*r, f[i*8+7]*r);
        p[tid + i * 256] = o;
    }
}

// ============================ launch ============================
extern "C" void kernel_launch(void* const* d_in, const int* in_sizes, int n_in,
                              void* d_out, int out_size)
{
    const float* x     = (const float*)d_in[0];
    const float* gamma = (const float*)d_in[1];
    const float* beta  = (const float*)d_in[2];
    const float* wq    = (const float*)d_in[3];
    const float* bq    = (const float*)d_in[4];
    const float* wk    = (const float*)d_in[5];
    const float* bk    = (const float*)d_in[6];
    const float* wv    = (const float*)d_in[7];
    const float* bv    = (const float*)d_in[8];
    const float* wo    = (const float*)d_in[9];
    const float* bo    = (const float*)d_in[10];
    float* out = (float*)d_out;

    unsigned short *p_hnT, *p_qT, *p_kT, *p_v, *p_oT, *p_w, *p_attnh;
    cudaGetSymbolAddress((void**)&p_hnT,   gh_hnT);
    cudaGetSymbolAddress((void**)&p_qT,    gh_qT);
    cudaGetSymbolAddress((void**)&p_kT,    gh_kT);
    cudaGetSymbolAddress((void**)&p_v,     gh_v);
    cudaGetSymbolAddress((void**)&p_oT,    gh_oT);
    cudaGetSymbolAddress((void**)&p_w,     gh_w);
    cudaGetSymbolAddress((void**)&p_attnh, gh_attn);

    cudaFuncSetAttribute(hgemm, cudaFuncAttributeMaxDynamicSharedMemorySize, SMEM_BYTES);

    const int WN = CCH * CCH;
    conv_w<<<(WN + 255)/256, 256>>>(wq, p_w + 0*(size_t)WN, WN);
    conv_w<<<(WN + 255)/256, 256>>>(wk, p_w + 1*(size_t)WN, WN);
    conv_w<<<(WN + 255)/256, 256>>>(wv, p_w + 2*(size_t)WN, WN);
    conv_w<<<(WN + 255)/256, 256>>>(wo, p_w + 3*(size_t)WN, WN);

    gn_stats<<<BATCH * 32, 256>>>(x, gamma, beta);
    norm_transpose<<<dim3(NSP/64, CCH/64, BATCH), 256>>>(x);

    const size_t sNC = (size_t)NSP * CCH;
    const size_t sAT = (size_t)NSP * NSP;
    const __half* hw   = (const __half*)p_w;
    const __half* hhnT = (const __half*)p_hnT;

    // qT[n][co] = sum_c hnT[n][c] * Wq[co][c] + bq[co]   (M=4096, N=512, K=512)
    const dim3 g_nq(CCH/128, NSP/128, BATCH);     // (4, 32, 4)
    hgemm<<<g_nq, 256, SMEM_BYTES>>>(hhnT, hw + 0*(size_t)WN, bq, nullptr, p_qT,
                                     CCH, CCH, CCH, CCH, sNC, 0, sNC, 1.f, 1, 0);
    hgemm<<<g_nq, 256, SMEM_BYTES>>>(hhnT, hw + 1*(size_t)WN, bk, nullptr, p_kT,
                                     CCH, CCH, CCH, CCH, sNC, 0, sNC, 1.f, 1, 0);

    // v[co][n] = sum_c Wv[co][c] * hnT[n][c] + bv[co]    (M=512, N=4096, K=512)
    const dim3 g_cn(NSP/128, CCH/128, BATCH);     // (32, 4, 4)
    hgemm<<<g_cn, 256, SMEM_BYTES>>>(hw + 2*(size_t)WN, hhnT, bv, nullptr, p_v,
                                     CCH, CCH, CCH, NSP, 0, sNC, sNC, 1.f, 0, 0);

    // scores[nq][nk] = scale * qT . kT   (M=N=4096, K=512), fp16 out into attn buffer
    const dim3 g_ss(NSP/128, NSP/128, BATCH);     // (32, 32, 4)
    hgemm<<<g_ss, 256, SMEM_BYTES>>>((const __half*)p_qT, (const __half*)p_kT,
                                     nullptr, nullptr, p_attnh,
                                     CCH, CCH, CCH, NSP, sNC, sNC, sAT,
                                     0.04419417382415922f, 0, 0);

    softmax_h<<<BATCH * NSP, 256>>>();

    // oT[nq][c] = sum_m attn[nq][m] * v[c][m]   (M=4096, N=512, K=4096)
    hgemm<<<g_nq, 256, SMEM_BYTES>>>((const __half*)p_attnh, (const __half*)p_v,
                                     nullptr, nullptr, p_oT,
                                     NSP, NSP, NSP, CCH, sAT, sNC, sNC, 1.f, 0, 0);

    // out[co][n] = Wo . oT + bo + x   (M=512, N=4096, K=512), fp32 out + residual
    hgemm<<<g_cn, 256, SMEM_BYTES>>>(hw + 3*(size_t)WN, (const __half*)p_oT, bo, x, out,
                                     CCH, CCH, CCH, NSP, 0, sNC, (size_t)CCH * NSP, 1.f, 0, 1);
}